// round 13
// baseline (speedup 1.0000x reference)
#include <cuda_runtime.h>
#include <cuda_fp16.h>

#define BB 8
#define HH 16
#define EE 1024
#define HD 64
#define SQ 1024
#define SK 2048

// fp16 scratch (allocation-free rule: __device__ globals)
__device__ __half g_chi_h[BB*SQ*EE];
__device__ __half g_eng_h[BB*SK*EE];
__device__ __half g_wq_p[EE*EE];        // [e][h*64+d], pre-scaled
__device__ __half g_wkv_p[EE*2048];     // [e][ K:0..1023 | V:1024..2047 ]
__device__ __half g_wo_h[EE*EE];        // [e][c]
__device__ __half g_qh[BB*HH*SQ*HD];    // [b][h][q][d]
__device__ __half g_kvh[2*BB*HH*SK*HD]; // [K|V][b][h][key][d]
__device__ __half g_ctx_h[BB*SQ*EE];    // [b][q][e]

// ---------------------------------------------------------------------------
// helpers
// ---------------------------------------------------------------------------
__device__ __forceinline__ unsigned packh2(float lo, float hi) {
    __half2 h = __floats2half2_rn(lo, hi);
    return *reinterpret_cast<unsigned*>(&h);
}
__device__ __forceinline__ unsigned sptr(const void* p) {
    return (unsigned)__cvta_generic_to_shared(p);
}
__device__ __forceinline__ void ldsm4(unsigned r[4], unsigned addr) {
    asm volatile("ldmatrix.sync.aligned.m8n8.x4.shared.b16 {%0,%1,%2,%3},[%4];"
        : "=r"(r[0]), "=r"(r[1]), "=r"(r[2]), "=r"(r[3]) : "r"(addr));
}
__device__ __forceinline__ void ldsm4t(unsigned r[4], unsigned addr) {
    asm volatile("ldmatrix.sync.aligned.m8n8.x4.trans.shared.b16 {%0,%1,%2,%3},[%4];"
        : "=r"(r[0]), "=r"(r[1]), "=r"(r[2]), "=r"(r[3]) : "r"(addr));
}
// fp32-accum fp16 MMA
__device__ __forceinline__ void mma16816(float c[4], const unsigned a[4],
                                         unsigned b0, unsigned b1) {
    asm volatile(
        "mma.sync.aligned.m16n8k16.row.col.f32.f16.f16.f32 "
        "{%0,%1,%2,%3},{%4,%5,%6,%7},{%8,%9},{%0,%1,%2,%3};"
        : "+f"(c[0]), "+f"(c[1]), "+f"(c[2]), "+f"(c[3])
        : "r"(a[0]), "r"(a[1]), "r"(a[2]), "r"(a[3]), "r"(b0), "r"(b1));
}
// fp16-accum fp16 MMA (C = 2 regs of packed halves)
__device__ __forceinline__ void mma16816h(unsigned c[2], const unsigned a[4],
                                          unsigned b0, unsigned b1) {
    asm volatile(
        "mma.sync.aligned.m16n8k16.row.col.f16.f16.f16.f16 "
        "{%0,%1},{%2,%3,%4,%5},{%6,%7},{%0,%1};"
        : "+r"(c[0]), "+r"(c[1])
        : "r"(a[0]), "r"(a[1]), "r"(a[2]), "r"(a[3]), "r"(b0), "r"(b1));
}
__device__ __forceinline__ void cpa16(unsigned s, const void* g) {
    asm volatile("cp.async.cg.shared.global [%0], [%1], 16;" :: "r"(s), "l"(g));
}
#define CP_COMMIT() asm volatile("cp.async.commit_group;")
#define CP_WAIT0()  asm volatile("cp.async.wait_group 0;" ::: "memory")
__device__ __forceinline__ unsigned ex2h2(unsigned x) {
    unsigned y;
    asm("ex2.approx.f16x2 %0, %1;" : "=r"(y) : "r"(x));
    return y;
}

// ---------------------------------------------------------------------------
// conversions
// ---------------------------------------------------------------------------
__global__ void f2h_act(const float* __restrict__ chi,
                        const float* __restrict__ eng)
{
    int blk = blockIdx.x;
    const float* in;
    __half* out;
    int base;
    if (blk < 4096) { in = chi; out = g_chi_h; base = blk; }
    else            { in = eng; out = g_eng_h; base = blk - 4096; }
    int i = (base * 256 + threadIdx.x) * 8;
    float4 a = *(const float4*)(in + i);
    float4 b = *(const float4*)(in + i + 4);
    unsigned u[4];
    u[0] = packh2(a.x, a.y); u[1] = packh2(a.z, a.w);
    u[2] = packh2(b.x, b.y); u[3] = packh2(b.z, b.w);
    *(uint4*)(out + i) = *(uint4*)u;
}

__global__ void f2h_wo(const float* __restrict__ wo)
{
    int i = (blockIdx.x * 256 + threadIdx.x) * 8;
    float4 a = *(const float4*)(wo + i);
    float4 b = *(const float4*)(wo + i + 4);
    unsigned u[4];
    u[0] = packh2(a.x, a.y); u[1] = packh2(a.z, a.w);
    u[2] = packh2(b.x, b.y); u[3] = packh2(b.z, b.w);
    *(uint4*)(g_wo_h + i) = *(uint4*)u;
}

// fused weight packing: Wq (scaled) -> g_wq_p; Wk, Wv -> g_wkv_p (V at +1024)
__global__ void wpack_all(const float* __restrict__ Wq,
                          const float* __restrict__ Wk,
                          const float* __restrict__ Wv,
                          float qscale)
{
    int blk = blockIdx.x;
    const float* W;
    __half* out;
    float scale = 1.f;
    int row_stride;
    if (blk < 1024)      { W = Wq; out = g_wq_p;         row_stride = EE;   scale = qscale; }
    else if (blk < 2048) { W = Wk; out = g_wkv_p;        row_stride = 2048; blk -= 1024; }
    else                 { W = Wv; out = g_wkv_p + 1024; row_stride = 2048; blk -= 2048; }
    int id = blk * 256 + threadIdx.x;
    int d4 = (id & 15) * 4;
    int e  = (id >> 4) & (EE - 1);
    int h  = id >> 14;
    float4 v = *(const float4*)(W + ((size_t)h * EE + e) * HD + d4);
    unsigned u[2];
    u[0] = packh2(v.x * scale, v.y * scale);
    u[1] = packh2(v.z * scale, v.w * scale);
    *(uint2*)(out + (size_t)e * row_stride + h * HD + d4) = *(uint2*)u;
}

// ---------------------------------------------------------------------------
// fp16 GEMM body v4: tile 128x128, BK=64, **128 threads / 4 warps, warp tile
// 64x64** (MMA:LDSM = 32:8 vs old 16:6 — shared-pipe pressure down 1.5x).
// Double-buffered cp.async, single sync per K-iter, 2 CTAs/SM (71680 B smem).
//   out col c: split=c>>10, h=(c>>6)&15, d=c&63
// ---------------------------------------------------------------------------
template<bool OUT_HALF>
__device__ __forceinline__ void gemm_body(
    const __half* __restrict__ X, const __half* __restrict__ W, int Wstride,
    void* __restrict__ outp, int Srows,
    long o_split, long o_b, int o_s, int o_h,
    int mt, int nt)
{
    extern __shared__ __half sm[];
    const unsigned smA = sptr(sm);           // 2 x 18432 B (128x72 halves)
    const unsigned smB = smA + 36864;        // 2 x 17408 B (64x136 halves)

    const int tid  = threadIdx.x;
    const int warp = tid >> 5, lane = tid & 31;
    const int g = lane >> 2, tig = lane & 3;
    const int i8 = lane & 7, sel = lane >> 3;
    const int mw = warp >> 1;                // 0..1  M band of 64
    const int nw = warp & 1;                 // 0..1  N band of 64
    const int gr0 = mt * 128;
    const int n0  = nt * 128;
    const int b   = gr0 / Srows;
    const int s0  = gr0 - b * Srows;

    const __half* Xb = X + (size_t)gr0 * EE;

    float acc[4][8][4];                      // 4 m16-tiles x 8 n8-tiles
    #pragma unroll
    for (int m = 0; m < 4; m++)
        #pragma unroll
        for (int j = 0; j < 8; j++)
            #pragma unroll
            for (int t = 0; t < 4; t++) acc[m][j][t] = 0.f;

    auto load_tiles = [&](int buf, int e0) {
        #pragma unroll
        for (int i = 0; i < 8; i++) {           // A: 128 x 64 halves
            int id = tid + i * 128;
            int row = id >> 3, c8 = (id & 7) * 8;
            cpa16(smA + buf*18432 + (row*72 + c8)*2,
                  Xb + (size_t)row * EE + e0 + c8);
        }
        #pragma unroll
        for (int i = 0; i < 8; i++) {           // B: 64 x 128 halves
            int id = tid + i * 128;
            int row = id >> 4, c8 = (id & 15) * 8;
            cpa16(smB + buf*17408 + (row*136 + c8)*2,
                  W + (size_t)(e0 + row) * Wstride + n0 + c8);
        }
    };

    load_tiles(0, 0);
    CP_COMMIT();

    for (int it = 0; it < EE/64; it++) {
        const int buf = it & 1;
        CP_WAIT0();
        __syncthreads();   // buf ready + all warps done reading buf^1
        if (it + 1 < EE/64) { load_tiles(buf ^ 1, (it + 1) * 64); CP_COMMIT(); }

        #pragma unroll
        for (int kb = 0; kb < 4; kb++) {
            unsigned a[4][4];
            #pragma unroll
            for (int m = 0; m < 4; m++)
                ldsm4(a[m], smA + buf*18432 +
                      ((mw*64 + m*16 + (sel&1)*8 + i8)*72
                       + kb*16 + (sel>>1)*8)*2);
            #pragma unroll
            for (int jj = 0; jj < 4; jj++) {
                unsigned bf[4];
                ldsm4t(bf, smB + buf*17408 +
                       ((kb*16 + (sel&1)*8 + i8)*136
                        + nw*64 + jj*16 + (sel>>1)*8)*2);
                #pragma unroll
                for (int m = 0; m < 4; m++) {
                    mma16816(acc[m][2*jj  ], a[m], bf[0], bf[1]);
                    mma16816(acc[m][2*jj+1], a[m], bf[2], bf[3]);
                }
            }
        }
    }

    #pragma unroll
    for (int m = 0; m < 4; m++) {
        const int r = s0 + mw*64 + m*16 + g;
        #pragma unroll
        for (int j = 0; j < 8; j++) {
            const int c = n0 + nw*64 + j*8 + tig*2;
            const int split = c >> 10, h = (c >> 6) & 15, d = c & 63;
            const size_t addr = (size_t)split * o_split + (size_t)b * o_b
                              + (size_t)r * o_s + (size_t)h * o_h + d;
            if (OUT_HALF) {
                __half* op = (__half*)outp;
                *(__half2*)&op[addr] = __floats2half2_rn(acc[m][j][0], acc[m][j][1]);
                *(__half2*)&op[addr + (size_t)8*o_s] =
                    __floats2half2_rn(acc[m][j][2], acc[m][j][3]);
            } else {
                float* op = (float*)outp;
                *(float2*)&op[addr] = make_float2(acc[m][j][0], acc[m][j][1]);
                *(float2*)&op[addr + (size_t)8*o_s] =
                    make_float2(acc[m][j][2], acc[m][j][3]);
            }
        }
    }
}

// Fused Q + KV projection: one launch, 2560 tiles of 128x128.
__global__ __launch_bounds__(128, 2) void gemm_qkv()
{
    int t = blockIdx.x;
    if (t < 512) {
        gemm_body<true>(g_chi_h, g_wq_p, EE, g_qh, SQ,
                        0L, (long)HH*SQ*HD, HD, SQ*HD,
                        t & 63, t >> 6);
    } else {
        int t2 = t - 512;
        gemm_body<true>(g_eng_h, g_wkv_p, 2048, g_kvh, SK,
                        (long)BB*HH*SK*HD, (long)HH*SK*HD, HD, SK*HD,
                        t2 & 127, t2 >> 7);
    }
}

// Output projection (fp32 out): 512 tiles
__global__ __launch_bounds__(128, 2) void gemm_o(float* __restrict__ out)
{
    int t = blockIdx.x;
    gemm_body<false>(g_ctx_h, g_wo_h, EE, out, BB*SQ,
                     0L, 0L, EE, HD,
                     t & 63, t >> 6);
}

// ---------------------------------------------------------------------------
// Flash attention v6 (unchanged, passing): 128 thr / 4 warps, q-tile 128
// (2 m16 bands/warp), k-tile 64, f16-accum S, per-16-key-chunk
// S->ex2->ones->PV pipeline, Q staged through K smem, 3 CTAs/SM. smem 36864 B
// ---------------------------------------------------------------------------
__global__ __launch_bounds__(128, 3) void attn_h6()
{
    extern __shared__ __half sm[];
    const unsigned smK = sptr(sm);        // 2 bufs x 9216 B  (also Q staging)
    const unsigned smV = smK + 18432;     // 2 bufs x 9216 B

    const int tid  = threadIdx.x;
    const int warp = tid >> 5, lane = tid & 31;
    const int g = lane >> 2, tig = lane & 3;
    const int i8 = lane & 7, sel = lane >> 3;
    const int q0 = blockIdx.x * 128;
    const int h  = blockIdx.y;
    const int b  = blockIdx.z;

    const __half* Qg = g_qh + ((size_t)(b*HH + h) * SQ + q0) * HD;
    const __half* Kg = g_kvh + (size_t)(b*HH + h) * SK * HD;
    const __half* Vg = g_kvh + (size_t)BB*HH*SK*HD + (size_t)(b*HH + h) * SK * HD;

    // stage Q through the K-buffer region
    #pragma unroll
    for (int i = 0; i < 8; i++) {
        int id = tid + i * 128;
        int row = id >> 3, c8 = (id & 7) * 8;
        *(uint4*)((char*)sm + (row*72 + c8)*2) =
            *(const uint4*)(Qg + (size_t)row * HD + c8);
    }
    __syncthreads();

    unsigned qf[2][4][4];
    #pragma unroll
    for (int band = 0; band < 2; band++)
        #pragma unroll
        for (int kb = 0; kb < 4; kb++)
            ldsm4(qf[band][kb],
                  smK + ((warp*32 + band*16 + (sel&1)*8 + i8)*72
                         + kb*16 + (sel>>1)*8)*2);
    __syncthreads();          // all Q reads done before K/V overwrite

    auto load_kv = [&](int buf, int k0) {
        #pragma unroll
        for (int i = 0; i < 4; i++) {
            int id = tid + i * 128;
            int row = id >> 3, c8 = (id & 7) * 8;
            cpa16(smK + buf*9216 + (row*72 + c8)*2,
                  Kg + (size_t)(k0 + row) * HD + c8);
            cpa16(smV + buf*9216 + (row*72 + c8)*2,
                  Vg + (size_t)(k0 + row) * HD + c8);
        }
    };

    load_kv(0, 0);
    CP_COMMIT();

    const unsigned ONES = 0x3C003C00u;   // half2(1,1)

    float O[2][8][4];
    float lacc[2][4];
    #pragma unroll
    for (int band = 0; band < 2; band++) {
        #pragma unroll
        for (int j = 0; j < 8; j++)
            #pragma unroll
            for (int t = 0; t < 4; t++) O[band][j][t] = 0.f;
        #pragma unroll
        for (int t = 0; t < 4; t++) lacc[band][t] = 0.f;
    }

    for (int kt = 0; kt < SK/64; kt++) {
        const int buf = kt & 1;
        CP_WAIT0();
        __syncthreads();
        if (kt + 1 < SK/64) { load_kv(buf ^ 1, (kt + 1) * 64); CP_COMMIT(); }

        #pragma unroll
        for (int jj = 0; jj < 4; jj++) {
            unsigned sh[2][4];
            #pragma unroll
            for (int band = 0; band < 2; band++)
                #pragma unroll
                for (int t = 0; t < 4; t++) sh[band][t] = 0u;

            #pragma unroll
            for (int kb = 0; kb < 4; kb++) {
                unsigned bf[4];
                ldsm4(bf, smK + buf*9216 +
                      ((jj*16 + (sel&1)*8 + i8)*72 + kb*16 + (sel>>1)*8)*2);
                #pragma unroll
                for (int band = 0; band < 2; band++) {
                    mma16816h(&sh[band][0], qf[band][kb], bf[0], bf[2]);
                    mma16816h(&sh[band][2], qf[band][kb], bf[1], bf[3]);
                }
            }

            #pragma unroll
            for (int band = 0; band < 2; band++) {
                #pragma unroll
                for (int t = 0; t < 4; t++) sh[band][t] = ex2h2(sh[band][t]);
                mma16816(lacc[band], sh[band], ONES, ONES);
            }

            #pragma unroll
            for (int jd = 0; jd < 4; jd++) {
                unsigned bf[4];
                ldsm4t(bf, smV + buf*9216 +
                       ((jj*16 + (sel&1)*8 + i8)*72 + jd*16 + (sel>>1)*8)*2);
                #pragma unroll
                for (int band = 0; band < 2; band++) {
                    mma16816(O[band][2*jd  ], sh[band], bf[0], bf[1]);
                    mma16816(O[band][2*jd+1], sh[band], bf[2], bf[3]);
                }
            }
        }
    }

    #pragma unroll
    for (int band = 0; band < 2; band++) {
        const float inv0 = 1.f / lacc[band][0];
        const float inv1 = 1.f / lacc[band][2];
        __half* Og = g_ctx_h
            + ((size_t)b * SQ + q0 + warp*32 + band*16 + g) * EE + h * HD;
        #pragma unroll
        for (int j = 0; j < 8; j++) {
            int c = j*8 + tig*2;
            *(__half2*)&Og[c] =
                __floats2half2_rn(O[band][j][0]*inv0, O[band][j][1]*inv0);
            *(__half2*)&Og[8*EE + c] =
                __floats2half2_rn(O[band][j][2]*inv1, O[band][j][3]*inv1);
        }
    }
}

// ---------------------------------------------------------------------------
extern "C" void kernel_launch(void* const* d_in, const int* in_sizes, int n_in,
                              void* d_out, int out_size)
{
    const float* eng = (const float*)d_in[0];   // [B, SK, E]
    const float* chi = (const float*)d_in[1];   // [B, SQ, E]
    const float* Wq  = (const float*)d_in[2];   // [H, E, HD]
    const float* Wk  = (const float*)d_in[3];
    const float* Wv  = (const float*)d_in[4];
    const float* Wo  = (const float*)d_in[5];   // [E, E]
    float* out = (float*)d_out;                 // [B, SQ, E]

    static bool attr_done = false;
    if (!attr_done) {
        cudaFuncSetAttribute(gemm_qkv,
            cudaFuncAttributeMaxDynamicSharedMemorySize, 71680);
        cudaFuncSetAttribute(gemm_o,
            cudaFuncAttributeMaxDynamicSharedMemorySize, 71680);
        cudaFuncSetAttribute(attn_h6,
            cudaFuncAttributeMaxDynamicSharedMemorySize, 36864);
        attr_done = true;
    }

    const float QSCALE = 0.18033688011112042f;   // 0.125 * log2(e)

    // 6 launches; gemm_qkv stays at our index 3 (the ncu-sampled slot).
    f2h_act  <<<12288, 256>>>(chi, eng);                  // 0
    wpack_all<<<3072,  256>>>(Wq, Wk, Wv, QSCALE);        // 1
    f2h_wo   <<<512,   256>>>(Wo);                        // 2
    gemm_qkv <<<2560,  128, 71680>>>();                   // 3
    attn_h6  <<<dim3(SQ/128, HH, BB), 128, 36864>>>();    // 4
    gemm_o   <<<512,   128, 71680>>>(out);                // 5
}

// round 14
// speedup vs baseline: 1.0014x; 1.0014x over previous
#include <cuda_runtime.h>
#include <cuda_fp16.h>

#define BB 8
#define HH 16
#define EE 1024
#define HD 64
#define SQ 1024
#define SK 2048

// fp16 scratch (allocation-free rule: __device__ globals)
__device__ __half g_chi_h[BB*SQ*EE];
__device__ __half g_eng_h[BB*SK*EE];
__device__ __half g_wq_p[EE*EE];        // [e][h*64+d], pre-scaled
__device__ __half g_wkv_p[EE*2048];     // [e][ K:0..1023 | V:1024..2047 ]
__device__ __half g_wo_h[EE*EE];        // [e][c]
__device__ __half g_qh[BB*HH*SQ*HD];    // [b][h][q][d]
__device__ __half g_kvh[2*BB*HH*SK*HD]; // [K|V][b][h][key][d]
__device__ __half g_ctx_h[BB*SQ*EE];    // [b][q][e]

// ---------------------------------------------------------------------------
// helpers
// ---------------------------------------------------------------------------
__device__ __forceinline__ unsigned packh2(float lo, float hi) {
    __half2 h = __floats2half2_rn(lo, hi);
    return *reinterpret_cast<unsigned*>(&h);
}
__device__ __forceinline__ unsigned sptr(const void* p) {
    return (unsigned)__cvta_generic_to_shared(p);
}
__device__ __forceinline__ void ldsm4(unsigned r[4], unsigned addr) {
    asm volatile("ldmatrix.sync.aligned.m8n8.x4.shared.b16 {%0,%1,%2,%3},[%4];"
        : "=r"(r[0]), "=r"(r[1]), "=r"(r[2]), "=r"(r[3]) : "r"(addr));
}
__device__ __forceinline__ void ldsm4t(unsigned r[4], unsigned addr) {
    asm volatile("ldmatrix.sync.aligned.m8n8.x4.trans.shared.b16 {%0,%1,%2,%3},[%4];"
        : "=r"(r[0]), "=r"(r[1]), "=r"(r[2]), "=r"(r[3]) : "r"(addr));
}
// fp32-accum fp16 MMA
__device__ __forceinline__ void mma16816(float c[4], const unsigned a[4],
                                         unsigned b0, unsigned b1) {
    asm volatile(
        "mma.sync.aligned.m16n8k16.row.col.f32.f16.f16.f32 "
        "{%0,%1,%2,%3},{%4,%5,%6,%7},{%8,%9},{%0,%1,%2,%3};"
        : "+f"(c[0]), "+f"(c[1]), "+f"(c[2]), "+f"(c[3])
        : "r"(a[0]), "r"(a[1]), "r"(a[2]), "r"(a[3]), "r"(b0), "r"(b1));
}
// fp16-accum fp16 MMA (C = 2 regs of packed halves)
__device__ __forceinline__ void mma16816h(unsigned c[2], const unsigned a[4],
                                          unsigned b0, unsigned b1) {
    asm volatile(
        "mma.sync.aligned.m16n8k16.row.col.f16.f16.f16.f16 "
        "{%0,%1},{%2,%3,%4,%5},{%6,%7},{%0,%1};"
        : "+r"(c[0]), "+r"(c[1])
        : "r"(a[0]), "r"(a[1]), "r"(a[2]), "r"(a[3]), "r"(b0), "r"(b1));
}
__device__ __forceinline__ void cpa16(unsigned s, const void* g) {
    asm volatile("cp.async.cg.shared.global [%0], [%1], 16;" :: "r"(s), "l"(g));
}
#define CP_COMMIT() asm volatile("cp.async.commit_group;")
#define CP_WAIT0()  asm volatile("cp.async.wait_group 0;" ::: "memory")
#define CP_WAIT1()  asm volatile("cp.async.wait_group 1;" ::: "memory")
__device__ __forceinline__ unsigned ex2h2(unsigned x) {
    unsigned y;
    asm("ex2.approx.f16x2 %0, %1;" : "=r"(y) : "r"(x));
    return y;
}

// ---------------------------------------------------------------------------
// conversions
// ---------------------------------------------------------------------------
__global__ void f2h_act(const float* __restrict__ chi,
                        const float* __restrict__ eng)
{
    int blk = blockIdx.x;
    const float* in;
    __half* out;
    int base;
    if (blk < 4096) { in = chi; out = g_chi_h; base = blk; }
    else            { in = eng; out = g_eng_h; base = blk - 4096; }
    int i = (base * 256 + threadIdx.x) * 8;
    float4 a = *(const float4*)(in + i);
    float4 b = *(const float4*)(in + i + 4);
    unsigned u[4];
    u[0] = packh2(a.x, a.y); u[1] = packh2(a.z, a.w);
    u[2] = packh2(b.x, b.y); u[3] = packh2(b.z, b.w);
    *(uint4*)(out + i) = *(uint4*)u;
}

__global__ void f2h_wo(const float* __restrict__ wo)
{
    int i = (blockIdx.x * 256 + threadIdx.x) * 8;
    float4 a = *(const float4*)(wo + i);
    float4 b = *(const float4*)(wo + i + 4);
    unsigned u[4];
    u[0] = packh2(a.x, a.y); u[1] = packh2(a.z, a.w);
    u[2] = packh2(b.x, b.y); u[3] = packh2(b.z, b.w);
    *(uint4*)(g_wo_h + i) = *(uint4*)u;
}

// fused weight packing: Wq (scaled) -> g_wq_p; Wk, Wv -> g_wkv_p (V at +1024)
__global__ void wpack_all(const float* __restrict__ Wq,
                          const float* __restrict__ Wk,
                          const float* __restrict__ Wv,
                          float qscale)
{
    int blk = blockIdx.x;
    const float* W;
    __half* out;
    float scale = 1.f;
    int row_stride;
    if (blk < 1024)      { W = Wq; out = g_wq_p;         row_stride = EE;   scale = qscale; }
    else if (blk < 2048) { W = Wk; out = g_wkv_p;        row_stride = 2048; blk -= 1024; }
    else                 { W = Wv; out = g_wkv_p + 1024; row_stride = 2048; blk -= 2048; }
    int id = blk * 256 + threadIdx.x;
    int d4 = (id & 15) * 4;
    int e  = (id >> 4) & (EE - 1);
    int h  = id >> 14;
    float4 v = *(const float4*)(W + ((size_t)h * EE + e) * HD + d4);
    unsigned u[2];
    u[0] = packh2(v.x * scale, v.y * scale);
    u[1] = packh2(v.z * scale, v.w * scale);
    *(uint2*)(out + (size_t)e * row_stride + h * HD + d4) = *(uint2*)u;
}

// ---------------------------------------------------------------------------
// fp16 GEMM body v5: R12 tiling (128x128 tile, 256 thr / 8 warps, warp tile
// 32x64, 127 regs) + **3-stage cp.async pipeline** (wait_group 1 -> each
// prefetch has ~2 compute windows to land). smem 3 x 35840 = 107520 B,
// 2 CTAs/SM (215 KB <= 228 KB).
// Per-buffer layout: A (128x72 halves, 18432 B) then B (64x136, 17408 B).
// ---------------------------------------------------------------------------
template<bool OUT_HALF>
__device__ __forceinline__ void gemm_body(
    const __half* __restrict__ X, const __half* __restrict__ W, int Wstride,
    void* __restrict__ outp, int Srows,
    long o_split, long o_b, int o_s, int o_h,
    int mt, int nt)
{
    extern __shared__ __half sm[];
    const unsigned smBase = sptr(sm);

    const int tid  = threadIdx.x;
    const int warp = tid >> 5, lane = tid & 31;
    const int g = lane >> 2, tig = lane & 3;
    const int i8 = lane & 7, sel = lane >> 3;
    const int mw = warp >> 1;                // 0..7  M band of 32
    const int nw = warp & 1;                 // 0..1  N band of 64
    const int gr0 = mt * 128;
    const int n0  = nt * 128;
    const int b   = gr0 / Srows;
    const int s0  = gr0 - b * Srows;

    const __half* Xb = X + (size_t)gr0 * EE;

    float acc[2][8][4];
    #pragma unroll
    for (int m = 0; m < 2; m++)
        #pragma unroll
        for (int j = 0; j < 8; j++)
            #pragma unroll
            for (int t = 0; t < 4; t++) acc[m][j][t] = 0.f;

    auto load_tiles = [&](int buf, int e0) {
        const unsigned sA = smBase + buf * 35840;
        const unsigned sB = sA + 18432;
        #pragma unroll
        for (int i = 0; i < 4; i++) {           // A: 128 x 64 halves
            int id = tid + i * 256;
            int row = id >> 3, c8 = (id & 7) * 8;
            cpa16(sA + (row*72 + c8)*2,
                  Xb + (size_t)row * EE + e0 + c8);
        }
        #pragma unroll
        for (int i = 0; i < 4; i++) {           // B: 64 x 128 halves
            int id = tid + i * 256;
            int row = id >> 4, c8 = (id & 15) * 8;
            cpa16(sB + (row*136 + c8)*2,
                  W + (size_t)(e0 + row) * Wstride + n0 + c8);
        }
    };

    load_tiles(0, 0);  CP_COMMIT();
    load_tiles(1, 64); CP_COMMIT();

    #pragma unroll 1
    for (int it = 0; it < EE/64; it++) {
        const int buf = (it == 0) ? 0 : ((it % 3));
        // (it%3 works since buffers cycle 0,1,2,0,1,2,... from the start)
        if (it + 1 < EE/64) CP_WAIT1(); else CP_WAIT0();
        __syncthreads();   // buf ready + all warps done with the reused buffer
        if (it + 2 < EE/64) { load_tiles((it + 2) % 3, (it + 2) * 64); CP_COMMIT(); }

        const unsigned sA = smBase + buf * 35840;
        const unsigned sB = sA + 18432;

        #pragma unroll
        for (int kb = 0; kb < 4; kb++) {
            unsigned a[2][4];
            #pragma unroll
            for (int m = 0; m < 2; m++)
                ldsm4(a[m], sA +
                      ((mw*32 + m*16 + (sel&1)*8 + i8)*72
                       + kb*16 + (sel>>1)*8)*2);
            #pragma unroll
            for (int jj = 0; jj < 4; jj++) {
                unsigned bf[4];
                ldsm4t(bf, sB +
                       ((kb*16 + (sel&1)*8 + i8)*136
                        + nw*64 + jj*16 + (sel>>1)*8)*2);
                #pragma unroll
                for (int m = 0; m < 2; m++) {
                    mma16816(acc[m][2*jj  ], a[m], bf[0], bf[1]);
                    mma16816(acc[m][2*jj+1], a[m], bf[2], bf[3]);
                }
            }
        }
    }

    #pragma unroll
    for (int m = 0; m < 2; m++) {
        const int r = s0 + mw*32 + m*16 + g;
        #pragma unroll
        for (int j = 0; j < 8; j++) {
            const int c = n0 + nw*64 + j*8 + tig*2;
            const int split = c >> 10, h = (c >> 6) & 15, d = c & 63;
            const size_t addr = (size_t)split * o_split + (size_t)b * o_b
                              + (size_t)r * o_s + (size_t)h * o_h + d;
            if (OUT_HALF) {
                __half* op = (__half*)outp;
                *(__half2*)&op[addr] = __floats2half2_rn(acc[m][j][0], acc[m][j][1]);
                *(__half2*)&op[addr + (size_t)8*o_s] =
                    __floats2half2_rn(acc[m][j][2], acc[m][j][3]);
            } else {
                float* op = (float*)outp;
                *(float2*)&op[addr] = make_float2(acc[m][j][0], acc[m][j][1]);
                *(float2*)&op[addr + (size_t)8*o_s] =
                    make_float2(acc[m][j][2], acc[m][j][3]);
            }
        }
    }
}

// Fused Q + KV projection: one launch, 2560 tiles of 128x128.
__global__ __launch_bounds__(256, 2) void gemm_qkv()
{
    int t = blockIdx.x;
    if (t < 512) {
        gemm_body<true>(g_chi_h, g_wq_p, EE, g_qh, SQ,
                        0L, (long)HH*SQ*HD, HD, SQ*HD,
                        t & 63, t >> 6);
    } else {
        int t2 = t - 512;
        gemm_body<true>(g_eng_h, g_wkv_p, 2048, g_kvh, SK,
                        (long)BB*HH*SK*HD, (long)HH*SK*HD, HD, SK*HD,
                        t2 & 127, t2 >> 7);
    }
}

// Output projection (fp32 out): 512 tiles
__global__ __launch_bounds__(256, 2) void gemm_o(float* __restrict__ out)
{
    int t = blockIdx.x;
    gemm_body<false>(g_ctx_h, g_wo_h, EE, out, BB*SQ,
                     0L, 0L, EE, HD,
                     t & 63, t >> 6);
}

// ---------------------------------------------------------------------------
// Flash attention v7: v6 + 3-stage K/V pipeline. 128 thr / 4 warps,
// q-tile 128 (2 m16 bands/warp), k-tile 64, f16-accum S, per-16-key-chunk
// S->ex2->ones->PV, Q staged through K smem. smem 3 x (9216+9216) = 55296 B,
// 3 CTAs/SM (166 KB, regs capped at 170 by launch_bounds).
// K buffers: smK + buf*9216 (3), V buffers: smK + 27648 + buf*9216 (3).
// ---------------------------------------------------------------------------
__global__ __launch_bounds__(128, 3) void attn_h7()
{
    extern __shared__ __half sm[];
    const unsigned smK = sptr(sm);        // 3 bufs x 9216 B (also Q staging)
    const unsigned smV = smK + 27648;     // 3 bufs x 9216 B

    const int tid  = threadIdx.x;
    const int warp = tid >> 5, lane = tid & 31;
    const int g = lane >> 2, tig = lane & 3;
    const int i8 = lane & 7, sel = lane >> 3;
    const int q0 = blockIdx.x * 128;
    const int h  = blockIdx.y;
    const int b  = blockIdx.z;

    const __half* Qg = g_qh + ((size_t)(b*HH + h) * SQ + q0) * HD;
    const __half* Kg = g_kvh + (size_t)(b*HH + h) * SK * HD;
    const __half* Vg = g_kvh + (size_t)BB*HH*SK*HD + (size_t)(b*HH + h) * SK * HD;

    // stage Q through the K-buffer region (18432 B needed, 27648 available)
    #pragma unroll
    for (int i = 0; i < 8; i++) {
        int id = tid + i * 128;
        int row = id >> 3, c8 = (id & 7) * 8;
        *(uint4*)((char*)sm + (row*72 + c8)*2) =
            *(const uint4*)(Qg + (size_t)row * HD + c8);
    }
    __syncthreads();

    unsigned qf[2][4][4];
    #pragma unroll
    for (int band = 0; band < 2; band++)
        #pragma unroll
        for (int kb = 0; kb < 4; kb++)
            ldsm4(qf[band][kb],
                  smK + ((warp*32 + band*16 + (sel&1)*8 + i8)*72
                         + kb*16 + (sel>>1)*8)*2);
    __syncthreads();          // all Q reads done before K/V overwrite

    auto load_kv = [&](int buf, int k0) {
        #pragma unroll
        for (int i = 0; i < 4; i++) {
            int id = tid + i * 128;
            int row = id >> 3, c8 = (id & 7) * 8;
            cpa16(smK + buf*9216 + (row*72 + c8)*2,
                  Kg + (size_t)(k0 + row) * HD + c8);
            cpa16(smV + buf*9216 + (row*72 + c8)*2,
                  Vg + (size_t)(k0 + row) * HD + c8);
        }
    };

    load_kv(0, 0);   CP_COMMIT();
    load_kv(1, 64);  CP_COMMIT();

    const unsigned ONES = 0x3C003C00u;   // half2(1,1)

    float O[2][8][4];
    float lacc[2][4];
    #pragma unroll
    for (int band = 0; band < 2; band++) {
        #pragma unroll
        for (int j = 0; j < 8; j++)
            #pragma unroll
            for (int t = 0; t < 4; t++) O[band][j][t] = 0.f;
        #pragma unroll
        for (int t = 0; t < 4; t++) lacc[band][t] = 0.f;
    }

    #pragma unroll 1
    for (int kt = 0; kt < SK/64; kt++) {
        const int buf = kt % 3;
        if (kt + 1 < SK/64) CP_WAIT1(); else CP_WAIT0();
        __syncthreads();
        if (kt + 2 < SK/64) { load_kv((kt + 2) % 3, (kt + 2) * 64); CP_COMMIT(); }

        #pragma unroll
        for (int jj = 0; jj < 4; jj++) {
            unsigned sh[2][4];
            #pragma unroll
            for (int band = 0; band < 2; band++)
                #pragma unroll
                for (int t = 0; t < 4; t++) sh[band][t] = 0u;

            #pragma unroll
            for (int kb = 0; kb < 4; kb++) {
                unsigned bf[4];
                ldsm4(bf, smK + buf*9216 +
                      ((jj*16 + (sel&1)*8 + i8)*72 + kb*16 + (sel>>1)*8)*2);
                #pragma unroll
                for (int band = 0; band < 2; band++) {
                    mma16816h(&sh[band][0], qf[band][kb], bf[0], bf[2]);
                    mma16816h(&sh[band][2], qf[band][kb], bf[1], bf[3]);
                }
            }

            #pragma unroll
            for (int band = 0; band < 2; band++) {
                #pragma unroll
                for (int t = 0; t < 4; t++) sh[band][t] = ex2h2(sh[band][t]);
                mma16816(lacc[band], sh[band], ONES, ONES);
            }

            #pragma unroll
            for (int jd = 0; jd < 4; jd++) {
                unsigned bf[4];
                ldsm4t(bf, smV + buf*9216 +
                       ((jj*16 + (sel&1)*8 + i8)*72 + jd*16 + (sel>>1)*8)*2);
                #pragma unroll
                for (int band = 0; band < 2; band++) {
                    mma16816(O[band][2*jd  ], sh[band], bf[0], bf[1]);
                    mma16816(O[band][2*jd+1], sh[band], bf[2], bf[3]);
                }
            }
        }
    }

    #pragma unroll
    for (int band = 0; band < 2; band++) {
        const float inv0 = 1.f / lacc[band][0];
        const float inv1 = 1.f / lacc[band][2];
        __half* Og = g_ctx_h
            + ((size_t)b * SQ + q0 + warp*32 + band*16 + g) * EE + h * HD;
        #pragma unroll
        for (int j = 0; j < 8; j++) {
            int c = j*8 + tig*2;
            *(__half2*)&Og[c] =
                __floats2half2_rn(O[band][j][0]*inv0, O[band][j][1]*inv0);
            *(__half2*)&Og[8*EE + c] =
                __floats2half2_rn(O[band][j][2]*inv1, O[band][j][3]*inv1);
        }
    }
}

// ---------------------------------------------------------------------------
extern "C" void kernel_launch(void* const* d_in, const int* in_sizes, int n_in,
                              void* d_out, int out_size)
{
    const float* eng = (const float*)d_in[0];   // [B, SK, E]
    const float* chi = (const float*)d_in[1];   // [B, SQ, E]
    const float* Wq  = (const float*)d_in[2];   // [H, E, HD]
    const float* Wk  = (const float*)d_in[3];
    const float* Wv  = (const float*)d_in[4];
    const float* Wo  = (const float*)d_in[5];   // [E, E]
    float* out = (float*)d_out;                 // [B, SQ, E]

    static bool attr_done = false;
    if (!attr_done) {
        cudaFuncSetAttribute(gemm_qkv,
            cudaFuncAttributeMaxDynamicSharedMemorySize, 107520);
        cudaFuncSetAttribute(gemm_o,
            cudaFuncAttributeMaxDynamicSharedMemorySize, 107520);
        cudaFuncSetAttribute(attn_h7,
            cudaFuncAttributeMaxDynamicSharedMemorySize, 55296);
        attr_done = true;
    }

    const float QSCALE = 0.18033688011112042f;   // 0.125 * log2(e)

    // 6 launches; gemm_qkv stays at our index 3 (the ncu-sampled slot).
    f2h_act  <<<12288, 256>>>(chi, eng);                  // 0
    wpack_all<<<3072,  256>>>(Wq, Wk, Wv, QSCALE);        // 1
    f2h_wo   <<<512,   256>>>(Wo);                        // 2
    gemm_qkv <<<2560,  256, 107520>>>();                  // 3
    attn_h7  <<<dim3(SQ/128, HH, BB), 128, 55296>>>();    // 4
    gemm_o   <<<512,   256, 107520>>>(out);               // 5
}

// round 16
// speedup vs baseline: 1.0362x; 1.0347x over previous
#include <cuda_runtime.h>
#include <cuda_fp16.h>

#define BB 8
#define HH 16
#define EE 1024
#define HD 64
#define SQ 1024
#define SK 2048

// fp16 scratch (allocation-free rule: __device__ globals)
__device__ __half g_chi_h[BB*SQ*EE];
__device__ __half g_eng_h[BB*SK*EE];
__device__ __half g_wq_p[EE*EE];        // [e][h*64+d], pre-scaled
__device__ __half g_wkv_p[EE*2048];     // [e][ K:0..1023 | V:1024..2047 ]
__device__ __half g_wo_h[EE*EE];        // [e][c]
__device__ __half g_qh[BB*HH*SQ*HD];    // [b][h][q][d]
__device__ __half g_kvh[2*BB*HH*SK*HD]; // [K|V][b][h][key][d]
__device__ __half g_ctx_h[BB*SQ*EE];    // [b][q][e]

// ---------------------------------------------------------------------------
// helpers
// ---------------------------------------------------------------------------
__device__ __forceinline__ unsigned packh2(float lo, float hi) {
    __half2 h = __floats2half2_rn(lo, hi);
    return *reinterpret_cast<unsigned*>(&h);
}
__device__ __forceinline__ unsigned sptr(const void* p) {
    return (unsigned)__cvta_generic_to_shared(p);
}
__device__ __forceinline__ void ldsm4(unsigned r[4], unsigned addr) {
    asm volatile("ldmatrix.sync.aligned.m8n8.x4.shared.b16 {%0,%1,%2,%3},[%4];"
        : "=r"(r[0]), "=r"(r[1]), "=r"(r[2]), "=r"(r[3]) : "r"(addr));
}
__device__ __forceinline__ void ldsm4t(unsigned r[4], unsigned addr) {
    asm volatile("ldmatrix.sync.aligned.m8n8.x4.trans.shared.b16 {%0,%1,%2,%3},[%4];"
        : "=r"(r[0]), "=r"(r[1]), "=r"(r[2]), "=r"(r[3]) : "r"(addr));
}
// fp32-accum fp16 MMA
__device__ __forceinline__ void mma16816(float c[4], const unsigned a[4],
                                         unsigned b0, unsigned b1) {
    asm volatile(
        "mma.sync.aligned.m16n8k16.row.col.f32.f16.f16.f32 "
        "{%0,%1,%2,%3},{%4,%5,%6,%7},{%8,%9},{%0,%1,%2,%3};"
        : "+f"(c[0]), "+f"(c[1]), "+f"(c[2]), "+f"(c[3])
        : "r"(a[0]), "r"(a[1]), "r"(a[2]), "r"(a[3]), "r"(b0), "r"(b1));
}
// fp16-accum fp16 MMA (C = 2 regs of packed halves)
__device__ __forceinline__ void mma16816h(unsigned c[2], const unsigned a[4],
                                          unsigned b0, unsigned b1) {
    asm volatile(
        "mma.sync.aligned.m16n8k16.row.col.f16.f16.f16.f16 "
        "{%0,%1},{%2,%3,%4,%5},{%6,%7},{%0,%1};"
        : "+r"(c[0]), "+r"(c[1])
        : "r"(a[0]), "r"(a[1]), "r"(a[2]), "r"(a[3]), "r"(b0), "r"(b1));
}
__device__ __forceinline__ void cpa16(unsigned s, const void* g) {
    asm volatile("cp.async.cg.shared.global [%0], [%1], 16;" :: "r"(s), "l"(g));
}
#define CP_COMMIT() asm volatile("cp.async.commit_group;")
#define CP_WAIT0()  asm volatile("cp.async.wait_group 0;" ::: "memory")
__device__ __forceinline__ unsigned ex2h2(unsigned x) {
    unsigned y;
    asm("ex2.approx.f16x2 %0, %1;" : "=r"(y) : "r"(x));
    return y;
}

// ---------------------------------------------------------------------------
// conversions
// ---------------------------------------------------------------------------
__global__ void f2h_act(const float* __restrict__ chi,
                        const float* __restrict__ eng)
{
    int blk = blockIdx.x;
    const float* in;
    __half* out;
    int base;
    if (blk < 4096) { in = chi; out = g_chi_h; base = blk; }
    else            { in = eng; out = g_eng_h; base = blk - 4096; }
    int i = (base * 256 + threadIdx.x) * 8;
    float4 a = *(const float4*)(in + i);
    float4 b = *(const float4*)(in + i + 4);
    unsigned u[4];
    u[0] = packh2(a.x, a.y); u[1] = packh2(a.z, a.w);
    u[2] = packh2(b.x, b.y); u[3] = packh2(b.z, b.w);
    *(uint4*)(out + i) = *(uint4*)u;
}

__global__ void f2h_wo(const float* __restrict__ wo)
{
    int i = (blockIdx.x * 256 + threadIdx.x) * 8;
    float4 a = *(const float4*)(wo + i);
    float4 b = *(const float4*)(wo + i + 4);
    unsigned u[4];
    u[0] = packh2(a.x, a.y); u[1] = packh2(a.z, a.w);
    u[2] = packh2(b.x, b.y); u[3] = packh2(b.z, b.w);
    *(uint4*)(g_wo_h + i) = *(uint4*)u;
}

// fused weight packing: Wq (scaled) -> g_wq_p; Wk, Wv -> g_wkv_p (V at +1024)
__global__ void wpack_all(const float* __restrict__ Wq,
                          const float* __restrict__ Wk,
                          const float* __restrict__ Wv,
                          float qscale)
{
    int blk = blockIdx.x;
    const float* W;
    __half* out;
    float scale = 1.f;
    int row_stride;
    if (blk < 1024)      { W = Wq; out = g_wq_p;         row_stride = EE;   scale = qscale; }
    else if (blk < 2048) { W = Wk; out = g_wkv_p;        row_stride = 2048; blk -= 1024; }
    else                 { W = Wv; out = g_wkv_p + 1024; row_stride = 2048; blk -= 2048; }
    int id = blk * 256 + threadIdx.x;
    int d4 = (id & 15) * 4;
    int e  = (id >> 4) & (EE - 1);
    int h  = id >> 14;
    float4 v = *(const float4*)(W + ((size_t)h * EE + e) * HD + d4);
    unsigned u[2];
    u[0] = packh2(v.x * scale, v.y * scale);
    u[1] = packh2(v.z * scale, v.w * scale);
    *(uint2*)(out + (size_t)e * row_stride + h * HD + d4) = *(uint2*)u;
}

// ---------------------------------------------------------------------------
// fp16 GEMM body v6b — attention-shaped CTAs (loader FIXED): tile 128(M)x64(N),
// BK=64, 128 threads / 4 warps (warp tile 32x64), double-buffered cp.async,
// single sync per K-iter.
// smem per buffer: A 128x72 halves (18432 B) + B 64x72 halves (9216 B)
//   = 27648 B; x2 = 55296 B -> 4 independent CTAs/SM.
// Loader: A = 1024 16B-chunks -> 8 iters of (row=id>>3, c8=(id&7)*8);
//         B =  512 16B-chunks -> 4 iters, same formula. (R15 bug: covered
//         only half the columns.)
// ---------------------------------------------------------------------------
template<bool OUT_HALF>
__device__ __forceinline__ void gemm_body(
    const __half* __restrict__ X, const __half* __restrict__ W, int Wstride,
    void* __restrict__ outp, int Srows,
    long o_split, long o_b, int o_s, int o_h,
    int mt, int nt)
{
    extern __shared__ __half sm[];
    const unsigned smBase = sptr(sm);

    const int tid  = threadIdx.x;
    const int warp = tid >> 5, lane = tid & 31;
    const int g = lane >> 2, tig = lane & 3;
    const int i8 = lane & 7, sel = lane >> 3;
    const int gr0 = mt * 128;
    const int n0  = nt * 64;
    const int b   = gr0 / Srows;
    const int s0  = gr0 - b * Srows;

    const __half* Xb = X + (size_t)gr0 * EE;

    float acc[2][8][4];
    #pragma unroll
    for (int m = 0; m < 2; m++)
        #pragma unroll
        for (int j = 0; j < 8; j++)
            #pragma unroll
            for (int t = 0; t < 4; t++) acc[m][j][t] = 0.f;

    auto load_tiles = [&](int buf, int e0) {
        const unsigned sA = smBase + buf * 27648;
        const unsigned sB = sA + 18432;
        #pragma unroll
        for (int i = 0; i < 8; i++) {           // A: 128 rows x 8 chunks
            int id = tid + i * 128;
            int row = id >> 3, c8 = (id & 7) * 8;
            cpa16(sA + (row*72 + c8)*2,
                  Xb + (size_t)row * EE + e0 + c8);
        }
        #pragma unroll
        for (int i = 0; i < 4; i++) {           // B: 64 rows x 8 chunks
            int id = tid + i * 128;
            int row = id >> 3, c8 = (id & 7) * 8;
            cpa16(sB + (row*72 + c8)*2,
                  W + (size_t)(e0 + row) * Wstride + n0 + c8);
        }
    };

    load_tiles(0, 0);
    CP_COMMIT();

    for (int it = 0; it < EE/64; it++) {
        const int buf = it & 1;
        CP_WAIT0();
        __syncthreads();   // buf ready + all warps done reading buf^1
        if (it + 1 < EE/64) { load_tiles(buf ^ 1, (it + 1) * 64); CP_COMMIT(); }

        const unsigned sA = smBase + buf * 27648;
        const unsigned sB = sA + 18432;

        #pragma unroll
        for (int kb = 0; kb < 4; kb++) {
            unsigned a[2][4];
            #pragma unroll
            for (int m = 0; m < 2; m++)
                ldsm4(a[m], sA +
                      ((warp*32 + m*16 + (sel&1)*8 + i8)*72
                       + kb*16 + (sel>>1)*8)*2);
            #pragma unroll
            for (int jj = 0; jj < 4; jj++) {
                unsigned bf[4];
                ldsm4t(bf, sB +
                       ((kb*16 + (sel&1)*8 + i8)*72
                        + jj*16 + (sel>>1)*8)*2);
                #pragma unroll
                for (int m = 0; m < 2; m++) {
                    mma16816(acc[m][2*jj  ], a[m], bf[0], bf[1]);
                    mma16816(acc[m][2*jj+1], a[m], bf[2], bf[3]);
                }
            }
        }
    }

    #pragma unroll
    for (int m = 0; m < 2; m++) {
        const int r = s0 + warp*32 + m*16 + g;
        #pragma unroll
        for (int j = 0; j < 8; j++) {
            const int c = n0 + j*8 + tig*2;
            const int split = c >> 10, h = (c >> 6) & 15, d = c & 63;
            const size_t addr = (size_t)split * o_split + (size_t)b * o_b
                              + (size_t)r * o_s + (size_t)h * o_h + d;
            if (OUT_HALF) {
                __half* op = (__half*)outp;
                *(__half2*)&op[addr] = __floats2half2_rn(acc[m][j][0], acc[m][j][1]);
                *(__half2*)&op[addr + (size_t)8*o_s] =
                    __floats2half2_rn(acc[m][j][2], acc[m][j][3]);
            } else {
                float* op = (float*)outp;
                *(float2*)&op[addr] = make_float2(acc[m][j][0], acc[m][j][1]);
                *(float2*)&op[addr + (size_t)8*o_s] =
                    make_float2(acc[m][j][2], acc[m][j][3]);
            }
        }
    }
}

// Fused Q + KV projection: one launch, 5120 tiles of 128x64.
//   tiles [0,1024):    Q  (64 mt x 16 nt)
//   tiles [1024,5120): KV (128 mt x 32 nt, cols 0..2047 -> K|V split)
__global__ __launch_bounds__(128, 4) void gemm_qkv()
{
    int t = blockIdx.x;
    if (t < 1024) {
        gemm_body<true>(g_chi_h, g_wq_p, EE, g_qh, SQ,
                        0L, (long)HH*SQ*HD, HD, SQ*HD,
                        t & 63, t >> 6);
    } else {
        int t2 = t - 1024;
        gemm_body<true>(g_eng_h, g_wkv_p, 2048, g_kvh, SK,
                        (long)BB*HH*SK*HD, (long)HH*SK*HD, HD, SK*HD,
                        t2 & 127, t2 >> 7);
    }
}

// Output projection (fp32 out): 1024 tiles of 128x64
__global__ __launch_bounds__(128, 4) void gemm_o(float* __restrict__ out)
{
    int t = blockIdx.x;
    gemm_body<false>(g_ctx_h, g_wo_h, EE, out, BB*SQ,
                     0L, 0L, EE, HD,
                     t & 63, t >> 6);
}

// ---------------------------------------------------------------------------
// Flash attention v6 (R11/R12 measured-best, unchanged): 128 thr / 4 warps,
// q-tile 128 (2 m16 bands/warp), k-tile 64, f16-accum S, per-16-key-chunk
// S->ex2->ones->PV, Q staged through K smem, 2-stage pipeline, 3 CTAs/SM.
// dyn smem: 36864 B
// ---------------------------------------------------------------------------
__global__ __launch_bounds__(128, 3) void attn_h6()
{
    extern __shared__ __half sm[];
    const unsigned smK = sptr(sm);        // 2 bufs x 9216 B  (also Q staging)
    const unsigned smV = smK + 18432;     // 2 bufs x 9216 B

    const int tid  = threadIdx.x;
    const int warp = tid >> 5, lane = tid & 31;
    const int g = lane >> 2, tig = lane & 3;
    const int i8 = lane & 7, sel = lane >> 3;
    const int q0 = blockIdx.x * 128;
    const int h  = blockIdx.y;
    const int b  = blockIdx.z;

    const __half* Qg = g_qh + ((size_t)(b*HH + h) * SQ + q0) * HD;
    const __half* Kg = g_kvh + (size_t)(b*HH + h) * SK * HD;
    const __half* Vg = g_kvh + (size_t)BB*HH*SK*HD + (size_t)(b*HH + h) * SK * HD;

    // stage Q through the K-buffer region
    #pragma unroll
    for (int i = 0; i < 8; i++) {
        int id = tid + i * 128;
        int row = id >> 3, c8 = (id & 7) * 8;
        *(uint4*)((char*)sm + (row*72 + c8)*2) =
            *(const uint4*)(Qg + (size_t)row * HD + c8);
    }
    __syncthreads();

    unsigned qf[2][4][4];
    #pragma unroll
    for (int band = 0; band < 2; band++)
        #pragma unroll
        for (int kb = 0; kb < 4; kb++)
            ldsm4(qf[band][kb],
                  smK + ((warp*32 + band*16 + (sel&1)*8 + i8)*72
                         + kb*16 + (sel>>1)*8)*2);
    __syncthreads();          // all Q reads done before K/V overwrite

    auto load_kv = [&](int buf, int k0) {
        #pragma unroll
        for (int i = 0; i < 4; i++) {
            int id = tid + i * 128;
            int row = id >> 3, c8 = (id & 7) * 8;
            cpa16(smK + buf*9216 + (row*72 + c8)*2,
                  Kg + (size_t)(k0 + row) * HD + c8);
            cpa16(smV + buf*9216 + (row*72 + c8)*2,
                  Vg + (size_t)(k0 + row) * HD + c8);
        }
    };

    load_kv(0, 0);
    CP_COMMIT();

    const unsigned ONES = 0x3C003C00u;   // half2(1,1)

    float O[2][8][4];
    float lacc[2][4];
    #pragma unroll
    for (int band = 0; band < 2; band++) {
        #pragma unroll
        for (int j = 0; j < 8; j++)
            #pragma unroll
            for (int t = 0; t < 4; t++) O[band][j][t] = 0.f;
        #pragma unroll
        for (int t = 0; t < 4; t++) lacc[band][t] = 0.f;
    }

    for (int kt = 0; kt < SK/64; kt++) {
        const int buf = kt & 1;
        CP_WAIT0();
        __syncthreads();
        if (kt + 1 < SK/64) { load_kv(buf ^ 1, (kt + 1) * 64); CP_COMMIT(); }

        #pragma unroll
        for (int jj = 0; jj < 4; jj++) {
            unsigned sh[2][4];
            #pragma unroll
            for (int band = 0; band < 2; band++)
                #pragma unroll
                for (int t = 0; t < 4; t++) sh[band][t] = 0u;

            #pragma unroll
            for (int kb = 0; kb < 4; kb++) {
                unsigned bf[4];
                ldsm4(bf, smK + buf*9216 +
                      ((jj*16 + (sel&1)*8 + i8)*72 + kb*16 + (sel>>1)*8)*2);
                #pragma unroll
                for (int band = 0; band < 2; band++) {
                    mma16816h(&sh[band][0], qf[band][kb], bf[0], bf[2]);
                    mma16816h(&sh[band][2], qf[band][kb], bf[1], bf[3]);
                }
            }

            #pragma unroll
            for (int band = 0; band < 2; band++) {
                #pragma unroll
                for (int t = 0; t < 4; t++) sh[band][t] = ex2h2(sh[band][t]);
                mma16816(lacc[band], sh[band], ONES, ONES);
            }

            #pragma unroll
            for (int jd = 0; jd < 4; jd++) {
                unsigned bf[4];
                ldsm4t(bf, smV + buf*9216 +
                       ((jj*16 + (sel&1)*8 + i8)*72 + jd*16 + (sel>>1)*8)*2);
                #pragma unroll
                for (int band = 0; band < 2; band++) {
                    mma16816(O[band][2*jd  ], sh[band], bf[0], bf[1]);
                    mma16816(O[band][2*jd+1], sh[band], bf[2], bf[3]);
                }
            }
        }
    }

    #pragma unroll
    for (int band = 0; band < 2; band++) {
        const float inv0 = 1.f / lacc[band][0];
        const float inv1 = 1.f / lacc[band][2];
        __half* Og = g_ctx_h
            + ((size_t)b * SQ + q0 + warp*32 + band*16 + g) * EE + h * HD;
        #pragma unroll
        for (int j = 0; j < 8; j++) {
            int c = j*8 + tig*2;
            *(__half2*)&Og[c] =
                __floats2half2_rn(O[band][j][0]*inv0, O[band][j][1]*inv0);
            *(__half2*)&Og[8*EE + c] =
                __floats2half2_rn(O[band][j][2]*inv1, O[band][j][3]*inv1);
        }
    }
}

// ---------------------------------------------------------------------------
extern "C" void kernel_launch(void* const* d_in, const int* in_sizes, int n_in,
                              void* d_out, int out_size)
{
    const float* eng = (const float*)d_in[0];   // [B, SK, E]
    const float* chi = (const float*)d_in[1];   // [B, SQ, E]
    const float* Wq  = (const float*)d_in[2];   // [H, E, HD]
    const float* Wk  = (const float*)d_in[3];
    const float* Wv  = (const float*)d_in[4];
    const float* Wo  = (const float*)d_in[5];   // [E, E]
    float* out = (float*)d_out;                 // [B, SQ, E]

    static bool attr_done = false;
    if (!attr_done) {
        cudaFuncSetAttribute(gemm_qkv,
            cudaFuncAttributeMaxDynamicSharedMemorySize, 55296);
        cudaFuncSetAttribute(gemm_o,
            cudaFuncAttributeMaxDynamicSharedMemorySize, 55296);
        cudaFuncSetAttribute(attn_h6,
            cudaFuncAttributeMaxDynamicSharedMemorySize, 36864);
        attr_done = true;
    }

    const float QSCALE = 0.18033688011112042f;   // 0.125 * log2(e)

    // 6 launches; gemm_qkv stays at our index 3 (the ncu-sampled slot).
    f2h_act  <<<12288, 256>>>(chi, eng);                  // 0
    wpack_all<<<3072,  256>>>(Wq, Wk, Wv, QSCALE);        // 1
    f2h_wo   <<<512,   256>>>(Wo);                        // 2
    gemm_qkv <<<5120,  128, 55296>>>();                   // 3
    attn_h6  <<<dim3(SQ/128, HH, BB), 128, 36864>>>();    // 4
    gemm_o   <<<1024,  128, 55296>>>(out);                // 5
}

// round 17
// speedup vs baseline: 1.0738x; 1.0363x over previous
#include <cuda_runtime.h>
#include <cuda_fp16.h>

#define BB 8
#define HH 16
#define EE 1024
#define HD 64
#define SQ 1024
#define SK 2048

// fp16 scratch (allocation-free rule: __device__ globals)
__device__ __half g_chi_h[BB*SQ*EE];
__device__ __half g_eng_h[BB*SK*EE];
__device__ __half g_wq_p[EE*EE];        // [e][h*64+d], pre-scaled
__device__ __half g_wkv_p[EE*2048];     // [e][ K:0..1023 | V:1024..2047 ]
__device__ __half g_wo_h[EE*EE];        // [e][c]
__device__ __half g_qh[BB*HH*SQ*HD];    // [b][h][q][d]
__device__ __half g_kvh[2*BB*HH*SK*HD]; // [K|V][b][h][key][d]
__device__ __half g_ctx_h[BB*SQ*EE];    // [b][q][e]

// ---------------------------------------------------------------------------
// helpers
// ---------------------------------------------------------------------------
__device__ __forceinline__ unsigned packh2(float lo, float hi) {
    __half2 h = __floats2half2_rn(lo, hi);
    return *reinterpret_cast<unsigned*>(&h);
}
__device__ __forceinline__ unsigned sptr(const void* p) {
    return (unsigned)__cvta_generic_to_shared(p);
}
__device__ __forceinline__ void ldsm4(unsigned r[4], unsigned addr) {
    asm volatile("ldmatrix.sync.aligned.m8n8.x4.shared.b16 {%0,%1,%2,%3},[%4];"
        : "=r"(r[0]), "=r"(r[1]), "=r"(r[2]), "=r"(r[3]) : "r"(addr));
}
__device__ __forceinline__ void ldsm4t(unsigned r[4], unsigned addr) {
    asm volatile("ldmatrix.sync.aligned.m8n8.x4.trans.shared.b16 {%0,%1,%2,%3},[%4];"
        : "=r"(r[0]), "=r"(r[1]), "=r"(r[2]), "=r"(r[3]) : "r"(addr));
}
// fp32-accum fp16 MMA
__device__ __forceinline__ void mma16816(float c[4], const unsigned a[4],
                                         unsigned b0, unsigned b1) {
    asm volatile(
        "mma.sync.aligned.m16n8k16.row.col.f32.f16.f16.f32 "
        "{%0,%1,%2,%3},{%4,%5,%6,%7},{%8,%9},{%0,%1,%2,%3};"
        : "+f"(c[0]), "+f"(c[1]), "+f"(c[2]), "+f"(c[3])
        : "r"(a[0]), "r"(a[1]), "r"(a[2]), "r"(a[3]), "r"(b0), "r"(b1));
}
// fp16-accum fp16 MMA (C = 2 regs of packed halves)
__device__ __forceinline__ void mma16816h(unsigned c[2], const unsigned a[4],
                                          unsigned b0, unsigned b1) {
    asm volatile(
        "mma.sync.aligned.m16n8k16.row.col.f16.f16.f16.f16 "
        "{%0,%1},{%2,%3,%4,%5},{%6,%7},{%0,%1};"
        : "+r"(c[0]), "+r"(c[1])
        : "r"(a[0]), "r"(a[1]), "r"(a[2]), "r"(a[3]), "r"(b0), "r"(b1));
}
__device__ __forceinline__ void cpa16(unsigned s, const void* g) {
    asm volatile("cp.async.cg.shared.global [%0], [%1], 16;" :: "r"(s), "l"(g));
}
#define CP_COMMIT() asm volatile("cp.async.commit_group;")
#define CP_WAIT0()  asm volatile("cp.async.wait_group 0;" ::: "memory")
__device__ __forceinline__ unsigned ex2h2(unsigned x) {
    unsigned y;
    asm("ex2.approx.f16x2 %0, %1;" : "=r"(y) : "r"(x));
    return y;
}

// ---------------------------------------------------------------------------
// ONE fused conversion/pack launch (block-range dispatch):
//   [0,4096):       chi  f32->f16
//   [4096,12288):   eng  f32->f16
//   [12288,12800):  Wo   f32->f16
//   [12800,13824):  Wq   pack [h][e][d]->[e][h*64+d], scaled
//   [13824,14848):  Wk   pack -> g_wkv_p (stride 2048)
//   [14848,15872):  Wv   pack -> g_wkv_p+1024
// ---------------------------------------------------------------------------
__global__ void conv_all(const float* __restrict__ chi,
                         const float* __restrict__ eng,
                         const float* __restrict__ wo,
                         const float* __restrict__ Wq,
                         const float* __restrict__ Wk,
                         const float* __restrict__ Wv,
                         float qscale)
{
    int blk = blockIdx.x;
    if (blk < 12800) {
        const float* in; __half* out; int base;
        if (blk < 4096)       { in = chi; out = g_chi_h; base = blk; }
        else if (blk < 12288) { in = eng; out = g_eng_h; base = blk - 4096; }
        else                  { in = wo;  out = g_wo_h;  base = blk - 12288; }
        int i = (base * 256 + threadIdx.x) * 8;
        float4 a = *(const float4*)(in + i);
        float4 b = *(const float4*)(in + i + 4);
        unsigned u[4];
        u[0] = packh2(a.x, a.y); u[1] = packh2(a.z, a.w);
        u[2] = packh2(b.x, b.y); u[3] = packh2(b.z, b.w);
        *(uint4*)(out + i) = *(uint4*)u;
    } else {
        int wblk = blk - 12800;
        const float* W; __half* out;
        float scale = 1.f; int row_stride;
        if (wblk < 1024)      { W = Wq; out = g_wq_p;         row_stride = EE;   scale = qscale; }
        else if (wblk < 2048) { W = Wk; out = g_wkv_p;        row_stride = 2048; wblk -= 1024; }
        else                  { W = Wv; out = g_wkv_p + 1024; row_stride = 2048; wblk -= 2048; }
        int id = wblk * 256 + threadIdx.x;
        int d4 = (id & 15) * 4;
        int e  = (id >> 4) & (EE - 1);
        int h  = id >> 14;
        float4 v = *(const float4*)(W + ((size_t)h * EE + e) * HD + d4);
        unsigned u[2];
        u[0] = packh2(v.x * scale, v.y * scale);
        u[1] = packh2(v.z * scale, v.w * scale);
        *(uint2*)(out + (size_t)e * row_stride + h * HD + d4) = *(uint2*)u;
    }
}

// ---------------------------------------------------------------------------
// fp16 GEMM body v7: tile 128(M)x64(N), BK=64, 128 thr / 4 warps (warp tile
// 32x64), 4 CTAs/SM (2 x 27648 B smem), single sync per K-iter, and
// **staggered prefetch**: chunk-0 MMAs are issued BEFORE the next tile's
// cp.async, so load-issue overlaps tensor-pipe drain instead of preceding it.
// ---------------------------------------------------------------------------
template<bool OUT_HALF>
__device__ __forceinline__ void gemm_body(
    const __half* __restrict__ X, const __half* __restrict__ W, int Wstride,
    void* __restrict__ outp, int Srows,
    long o_split, long o_b, int o_s, int o_h,
    int mt, int nt)
{
    extern __shared__ __half sm[];
    const unsigned smBase = sptr(sm);

    const int tid  = threadIdx.x;
    const int warp = tid >> 5, lane = tid & 31;
    const int g = lane >> 2, tig = lane & 3;
    const int i8 = lane & 7, sel = lane >> 3;
    const int gr0 = mt * 128;
    const int n0  = nt * 64;
    const int b   = gr0 / Srows;
    const int s0  = gr0 - b * Srows;

    const __half* Xb = X + (size_t)gr0 * EE;

    float acc[2][8][4];
    #pragma unroll
    for (int m = 0; m < 2; m++)
        #pragma unroll
        for (int j = 0; j < 8; j++)
            #pragma unroll
            for (int t = 0; t < 4; t++) acc[m][j][t] = 0.f;

    auto load_tiles = [&](int buf, int e0) {
        const unsigned sA = smBase + buf * 27648;
        const unsigned sB = sA + 18432;
        #pragma unroll
        for (int i = 0; i < 8; i++) {           // A: 128 rows x 8 chunks
            int id = tid + i * 128;
            int row = id >> 3, c8 = (id & 7) * 8;
            cpa16(sA + (row*72 + c8)*2,
                  Xb + (size_t)row * EE + e0 + c8);
        }
        #pragma unroll
        for (int i = 0; i < 4; i++) {           // B: 64 rows x 8 chunks
            int id = tid + i * 128;
            int row = id >> 3, c8 = (id & 7) * 8;
            cpa16(sB + (row*72 + c8)*2,
                  W + (size_t)(e0 + row) * Wstride + n0 + c8);
        }
    };

    load_tiles(0, 0);
    CP_COMMIT();

    for (int it = 0; it < EE/64; it++) {
        const int buf = it & 1;
        CP_WAIT0();
        __syncthreads();   // buf ready + all warps done reading buf^1

        const unsigned sA = smBase + buf * 27648;
        const unsigned sB = sA + 18432;

        auto compute_kb = [&](int kb) {
            unsigned a[2][4];
            #pragma unroll
            for (int m = 0; m < 2; m++)
                ldsm4(a[m], sA +
                      ((warp*32 + m*16 + (sel&1)*8 + i8)*72
                       + kb*16 + (sel>>1)*8)*2);
            #pragma unroll
            for (int jj = 0; jj < 4; jj++) {
                unsigned bf[4];
                ldsm4t(bf, sB +
                       ((kb*16 + (sel&1)*8 + i8)*72
                        + jj*16 + (sel>>1)*8)*2);
                #pragma unroll
                for (int m = 0; m < 2; m++) {
                    mma16816(acc[m][2*jj  ], a[m], bf[0], bf[1]);
                    mma16816(acc[m][2*jj+1], a[m], bf[2], bf[3]);
                }
            }
        };

        compute_kb(0);     // fill the tensor queue first...
        if (it + 1 < EE/64) { load_tiles(buf ^ 1, (it + 1) * 64); CP_COMMIT(); }
        #pragma unroll     // ...then loads issue under tensor-pipe drain
        for (int kb = 1; kb < 4; kb++) compute_kb(kb);
    }

    #pragma unroll
    for (int m = 0; m < 2; m++) {
        const int r = s0 + warp*32 + m*16 + g;
        #pragma unroll
        for (int j = 0; j < 8; j++) {
            const int c = n0 + j*8 + tig*2;
            const int split = c >> 10, h = (c >> 6) & 15, d = c & 63;
            const size_t addr = (size_t)split * o_split + (size_t)b * o_b
                              + (size_t)r * o_s + (size_t)h * o_h + d;
            if (OUT_HALF) {
                __half* op = (__half*)outp;
                *(__half2*)&op[addr] = __floats2half2_rn(acc[m][j][0], acc[m][j][1]);
                *(__half2*)&op[addr + (size_t)8*o_s] =
                    __floats2half2_rn(acc[m][j][2], acc[m][j][3]);
            } else {
                float* op = (float*)outp;
                *(float2*)&op[addr] = make_float2(acc[m][j][0], acc[m][j][1]);
                *(float2*)&op[addr + (size_t)8*o_s] =
                    make_float2(acc[m][j][2], acc[m][j][3]);
            }
        }
    }
}

// Fused Q + KV projection: one launch, 5120 tiles of 128x64.
__global__ __launch_bounds__(128, 4) void gemm_qkv()
{
    int t = blockIdx.x;
    if (t < 1024) {
        gemm_body<true>(g_chi_h, g_wq_p, EE, g_qh, SQ,
                        0L, (long)HH*SQ*HD, HD, SQ*HD,
                        t & 63, t >> 6);
    } else {
        int t2 = t - 1024;
        gemm_body<true>(g_eng_h, g_wkv_p, 2048, g_kvh, SK,
                        (long)BB*HH*SK*HD, (long)HH*SK*HD, HD, SK*HD,
                        t2 & 127, t2 >> 7);
    }
}

// Output projection (fp32 out): 1024 tiles of 128x64
__global__ __launch_bounds__(128, 4) void gemm_o(float* __restrict__ out)
{
    int t = blockIdx.x;
    gemm_body<false>(g_ctx_h, g_wo_h, EE, out, BB*SQ,
                     0L, 0L, EE, HD,
                     t & 63, t >> 6);
}

// ---------------------------------------------------------------------------
// Flash attention v8 = v6 + staggered prefetch: chunk-0 of S/PV is computed
// before load_kv(next) is issued. 128 thr / 4 warps, q-tile 128 (2 m16
// bands/warp), k-tile 64, f16-accum S, per-16-key-chunk S->ex2->ones->PV,
// Q staged through K smem, 2-stage pipeline, 3 CTAs/SM. smem 36864 B.
// ---------------------------------------------------------------------------
__global__ __launch_bounds__(128, 3) void attn_h8()
{
    extern __shared__ __half sm[];
    const unsigned smK = sptr(sm);        // 2 bufs x 9216 B  (also Q staging)
    const unsigned smV = smK + 18432;     // 2 bufs x 9216 B

    const int tid  = threadIdx.x;
    const int warp = tid >> 5, lane = tid & 31;
    const int g = lane >> 2, tig = lane & 3;
    const int i8 = lane & 7, sel = lane >> 3;
    const int q0 = blockIdx.x * 128;
    const int h  = blockIdx.y;
    const int b  = blockIdx.z;

    const __half* Qg = g_qh + ((size_t)(b*HH + h) * SQ + q0) * HD;
    const __half* Kg = g_kvh + (size_t)(b*HH + h) * SK * HD;
    const __half* Vg = g_kvh + (size_t)BB*HH*SK*HD + (size_t)(b*HH + h) * SK * HD;

    // stage Q through the K-buffer region
    #pragma unroll
    for (int i = 0; i < 8; i++) {
        int id = tid + i * 128;
        int row = id >> 3, c8 = (id & 7) * 8;
        *(uint4*)((char*)sm + (row*72 + c8)*2) =
            *(const uint4*)(Qg + (size_t)row * HD + c8);
    }
    __syncthreads();

    unsigned qf[2][4][4];
    #pragma unroll
    for (int band = 0; band < 2; band++)
        #pragma unroll
        for (int kb = 0; kb < 4; kb++)
            ldsm4(qf[band][kb],
                  smK + ((warp*32 + band*16 + (sel&1)*8 + i8)*72
                         + kb*16 + (sel>>1)*8)*2);
    __syncthreads();          // all Q reads done before K/V overwrite

    auto load_kv = [&](int buf, int k0) {
        #pragma unroll
        for (int i = 0; i < 4; i++) {
            int id = tid + i * 128;
            int row = id >> 3, c8 = (id & 7) * 8;
            cpa16(smK + buf*9216 + (row*72 + c8)*2,
                  Kg + (size_t)(k0 + row) * HD + c8);
            cpa16(smV + buf*9216 + (row*72 + c8)*2,
                  Vg + (size_t)(k0 + row) * HD + c8);
        }
    };

    load_kv(0, 0);
    CP_COMMIT();

    const unsigned ONES = 0x3C003C00u;   // half2(1,1)

    float O[2][8][4];
    float lacc[2][4];
    #pragma unroll
    for (int band = 0; band < 2; band++) {
        #pragma unroll
        for (int j = 0; j < 8; j++)
            #pragma unroll
            for (int t = 0; t < 4; t++) O[band][j][t] = 0.f;
        #pragma unroll
        for (int t = 0; t < 4; t++) lacc[band][t] = 0.f;
    }

    for (int kt = 0; kt < SK/64; kt++) {
        const int buf = kt & 1;
        CP_WAIT0();
        __syncthreads();

        auto do_chunk = [&](int jj) {
            unsigned sh[2][4];
            #pragma unroll
            for (int band = 0; band < 2; band++)
                #pragma unroll
                for (int t = 0; t < 4; t++) sh[band][t] = 0u;

            #pragma unroll
            for (int kb = 0; kb < 4; kb++) {
                unsigned bf[4];
                ldsm4(bf, smK + buf*9216 +
                      ((jj*16 + (sel&1)*8 + i8)*72 + kb*16 + (sel>>1)*8)*2);
                #pragma unroll
                for (int band = 0; band < 2; band++) {
                    mma16816h(&sh[band][0], qf[band][kb], bf[0], bf[2]);
                    mma16816h(&sh[band][2], qf[band][kb], bf[1], bf[3]);
                }
            }

            #pragma unroll
            for (int band = 0; band < 2; band++) {
                #pragma unroll
                for (int t = 0; t < 4; t++) sh[band][t] = ex2h2(sh[band][t]);
                mma16816(lacc[band], sh[band], ONES, ONES);
            }

            #pragma unroll
            for (int jd = 0; jd < 4; jd++) {
                unsigned bf[4];
                ldsm4t(bf, smV + buf*9216 +
                       ((jj*16 + (sel&1)*8 + i8)*72 + jd*16 + (sel>>1)*8)*2);
                #pragma unroll
                for (int band = 0; band < 2; band++) {
                    mma16816(O[band][2*jd  ], sh[band], bf[0], bf[1]);
                    mma16816(O[band][2*jd+1], sh[band], bf[2], bf[3]);
                }
            }
        };

        do_chunk(0);       // fill the tensor queue first...
        if (kt + 1 < SK/64) { load_kv(buf ^ 1, (kt + 1) * 64); CP_COMMIT(); }
        #pragma unroll     // ...then loads issued under tensor-pipe drain
        for (int jj = 1; jj < 4; jj++) do_chunk(jj);
    }

    #pragma unroll
    for (int band = 0; band < 2; band++) {
        const float inv0 = 1.f / lacc[band][0];
        const float inv1 = 1.f / lacc[band][2];
        __half* Og = g_ctx_h
            + ((size_t)b * SQ + q0 + warp*32 + band*16 + g) * EE + h * HD;
        #pragma unroll
        for (int j = 0; j < 8; j++) {
            int c = j*8 + tig*2;
            *(__half2*)&Og[c] =
                __floats2half2_rn(O[band][j][0]*inv0, O[band][j][1]*inv0);
            *(__half2*)&Og[8*EE + c] =
                __floats2half2_rn(O[band][j][2]*inv1, O[band][j][3]*inv1);
        }
    }
}

// ---------------------------------------------------------------------------
extern "C" void kernel_launch(void* const* d_in, const int* in_sizes, int n_in,
                              void* d_out, int out_size)
{
    const float* eng = (const float*)d_in[0];   // [B, SK, E]
    const float* chi = (const float*)d_in[1];   // [B, SQ, E]
    const float* Wq  = (const float*)d_in[2];   // [H, E, HD]
    const float* Wk  = (const float*)d_in[3];
    const float* Wv  = (const float*)d_in[4];
    const float* Wo  = (const float*)d_in[5];   // [E, E]
    float* out = (float*)d_out;                 // [B, SQ, E]

    static bool attr_done = false;
    if (!attr_done) {
        cudaFuncSetAttribute(gemm_qkv,
            cudaFuncAttributeMaxDynamicSharedMemorySize, 55296);
        cudaFuncSetAttribute(gemm_o,
            cudaFuncAttributeMaxDynamicSharedMemorySize, 55296);
        cudaFuncSetAttribute(attn_h8,
            cudaFuncAttributeMaxDynamicSharedMemorySize, 36864);
        attr_done = true;
    }

    const float QSCALE = 0.18033688011112042f;   // 0.125 * log2(e)

    // 4 launches (fused conversions save ~2 graph nodes of overhead).
    conv_all <<<15872, 256>>>(chi, eng, Wo, Wq, Wk, Wv, QSCALE);  // 0
    gemm_qkv <<<5120,  128, 55296>>>();                           // 1
    attn_h8  <<<dim3(SQ/128, HH, BB), 128, 36864>>>();            // 2
    gemm_o   <<<1024,  128, 55296>>>(out);                        // 3
}